// round 9
// baseline (speedup 1.0000x reference)
#include <cuda_runtime.h>
#include <cuda_bf16.h>

#define THREADS 256

// Codebook k (k=0..15) has element g = +1 iff bit (3-g) of k is set
// (itertools.product([-1,1], repeat=4) order) -> signed butterflies, no loads.

__global__ void __launch_bounds__(THREADS)
gq_kernel(const float4* __restrict__ x,
          const float4* __restrict__ gum,
          const float* __restrict__ log_temp,
          float4* __restrict__ out,
          int n_groups)
{
    // Stride-5 float4 padding: thread t's 4 vectors live at sg[t*5 + j].
    // Read banks per 8-lane phase = {0,20,8,28,16,4,24,12} -> conflict-free.
    __shared__ float4 sg[THREADS * 5];

    int tid = threadIdx.x;
    int block_base = blockIdx.x * THREADS;   // first group owned by this block
    int gid = block_base + tid;

    // Coalesced cooperative load of this block's gumbel slab (THREADS*4 float4,
    // 16 KB). 4 wavefronts per LDG.128 instead of 16 for the strided pattern.
    {
        const float4* gslab = gum + (size_t)block_base * 4;
        int remaining = n_groups - block_base;
        int nvec = (remaining >= THREADS) ? THREADS * 4
                                          : (remaining > 0 ? remaining * 4 : 0);
#pragma unroll
        for (int k = 0; k < 4; k++) {
            int idx = tid + k * THREADS;
            if (idx < nvec) {
                float4 v = gslab[idx];
                sg[(idx >> 2) * 5 + (idx & 3)] = v;
            }
        }
    }

    float4 z = make_float4(0.f, 0.f, 0.f, 0.f);
    if (gid < n_groups) z = x[gid];

    __syncthreads();

    if (gid >= n_groups) return;

    float4 g0 = sg[tid * 5 + 0];
    float4 g1 = sg[tid * 5 + 1];
    float4 g2 = sg[tid * 5 + 2];
    float4 g3 = sg[tid * 5 + 3];

    float tau = __expf(*log_temp);
    tau = fminf(fmaxf(tau, 0.05f), 5.0f);
    float it = __frcp_rn(tau);

    const float LOG2E = 1.4426950408889634f;
    float pm = 2.0f * it * LOG2E;   // scales the dot term
    float qm = it * LOG2E;          // scales the gumbel term

    float gv[16] = { g0.x, g0.y, g0.z, g0.w,
                     g1.x, g1.y, g1.z, g1.w,
                     g2.x, g2.y, g2.z, g2.w,
                     g3.x, g3.y, g3.z, g3.w };

    // Forward butterfly: d[k] = sum_g sign(k,g) * z[g]
    //   bit0 <-> z.w, bit1 <-> z.z, bit2 <-> z.y, bit3 <-> z.x
    float t0 = -z.z - z.w;
    float t1 = -z.z + z.w;
    float t2 =  z.z - z.w;
    float t3 =  z.z + z.w;

    float u[8];
    u[0] = t0 - z.y;  u[1] = t1 - z.y;  u[2] = t2 - z.y;  u[3] = t3 - z.y;
    u[4] = t0 + z.y;  u[5] = t1 + z.y;  u[6] = t2 + z.y;  u[7] = t3 + z.y;

    // softmax((logits+g)/tau) == softmax((2 z.c_k + g_k)/tau): -|z|^2 and
    // -|c|^2 are uniform over k and cancel. No max-shift needed: worst-case
    // exp2 exponent magnitude ~65 << 128.
    float e[16];
#pragma unroll
    for (int j = 0; j < 8; j++) {
        float dlo = u[j] - z.x;   // k = j      (bit3 = 0)
        float dhi = u[j] + z.x;   // k = j + 8  (bit3 = 1)
        e[j]     = exp2f(fmaf(dlo, pm, gv[j]     * qm));
        e[j + 8] = exp2f(fmaf(dhi, pm, gv[j + 8] * qm));
    }

    // Inverse butterfly: q_g = sum_k sign(k,g) e_k; denominator S is free.
    float p0 = e[0]  + e[1],  m0 = e[1]  - e[0];
    float p1 = e[2]  + e[3],  m1 = e[3]  - e[2];
    float p2 = e[4]  + e[5],  m2 = e[5]  - e[4];
    float p3 = e[6]  + e[7],  m3 = e[7]  - e[6];
    float p4 = e[8]  + e[9],  m4 = e[9]  - e[8];
    float p5 = e[10] + e[11], m5 = e[11] - e[10];
    float p6 = e[12] + e[13], m6 = e[13] - e[12];
    float p7 = e[14] + e[15], m7 = e[15] - e[14];

    float q3 = ((m0 + m1) + (m2 + m3)) + ((m4 + m5) + (m6 + m7)); // g=3

    float P0 = p0 + p1, M0 = p1 - p0;
    float P1 = p2 + p3, M1 = p3 - p2;
    float P2 = p4 + p5, M2 = p5 - p4;
    float P3 = p6 + p7, M3 = p7 - p6;

    float q2 = (M0 + M1) + (M2 + M3);                              // g=2

    float Q0 = P0 + P1, R0 = P1 - P0;
    float Q1 = P2 + P3, R1 = P3 - P2;

    float q1 = R0 + R1;                                            // g=1
    float q0 = Q1 - Q0;                                            // g=0
    float S  = Q0 + Q1;

    float rs = __frcp_rn(S);
    out[gid] = make_float4(q0 * rs, q1 * rs, q2 * rs, q3 * rs);
}

extern "C" void kernel_launch(void* const* d_in, const int* in_sizes, int n_in,
                              void* d_out, int out_size)
{
    const float* x        = (const float*)d_in[0];  // [B,S,D]
    const float* gumbel   = (const float*)d_in[1];  // [B,S,NG,NC]
    // d_in[2] = codebook: hypercube structure used analytically, no load needed
    const float* log_temp = (const float*)d_in[3];  // scalar

    float* out = (float*)d_out;

    int ng = in_sizes[0] / 4;   // B*S*D/4 = 2,097,152 groups

    int blocks = (ng + THREADS - 1) / THREADS;

    gq_kernel<<<blocks, THREADS>>>((const float4*)x,
                                   (const float4*)gumbel,
                                   log_temp,
                                   (float4*)out,
                                   ng);
}

// round 10
// speedup vs baseline: 1.2119x; 1.2119x over previous
#include <cuda_runtime.h>
#include <cuda_bf16.h>

#define THREADS 256

// Codebook k (k=0..15) has element g = +1 iff bit (3-g) of k is set
// (itertools.product([-1,1], repeat=4) order) -> signed butterflies, no
// codebook loads at all.
//
// Pure single-pass stream (201 MB, zero reuse) -> use streaming (evict-first)
// cache ops on every global access so the stream doesn't thrash L2.

__global__ void __launch_bounds__(THREADS)
gq_kernel(const float4* __restrict__ x,
          const float4* __restrict__ gum,
          const float* __restrict__ log_temp,
          float4* __restrict__ out)
{
    int gid = blockIdx.x * THREADS + threadIdx.x;   // grid covers n exactly

    // Front-batched: 5 independent LDG.128 in flight, streaming policy.
    float4 z  = __ldcs(&x[gid]);
    float4 g0 = __ldcs(&gum[gid * 4 + 0]);
    float4 g1 = __ldcs(&gum[gid * 4 + 1]);
    float4 g2 = __ldcs(&gum[gid * 4 + 2]);
    float4 g3 = __ldcs(&gum[gid * 4 + 3]);

    float tau = __expf(*log_temp);
    tau = fminf(fmaxf(tau, 0.05f), 5.0f);
    float it = __frcp_rn(tau);

    const float LOG2E = 1.4426950408889634f;
    float pm = 2.0f * it * LOG2E;   // scales the dot term
    float qm = it * LOG2E;          // scales the gumbel term

    float gv[16] = { g0.x, g0.y, g0.z, g0.w,
                     g1.x, g1.y, g1.z, g1.w,
                     g2.x, g2.y, g2.z, g2.w,
                     g3.x, g3.y, g3.z, g3.w };

    // Forward butterfly: d[k] = sum_g sign(k,g) * z[g]
    //   bit0 <-> z.w, bit1 <-> z.z, bit2 <-> z.y, bit3 <-> z.x
    float t0 = -z.z - z.w;
    float t1 = -z.z + z.w;
    float t2 =  z.z - z.w;
    float t3 =  z.z + z.w;

    float u[8];
    u[0] = t0 - z.y;  u[1] = t1 - z.y;  u[2] = t2 - z.y;  u[3] = t3 - z.y;
    u[4] = t0 + z.y;  u[5] = t1 + z.y;  u[6] = t2 + z.y;  u[7] = t3 + z.y;

    // softmax((logits+g)/tau) == softmax((2 z.c_k + g_k)/tau): -|z|^2 and
    // -|c|^2 are uniform over k and cancel. No max-shift: worst-case exp2
    // exponent magnitude ~65 << 128 (fp32 range).
    float e[16];
#pragma unroll
    for (int j = 0; j < 8; j++) {
        float dlo = u[j] - z.x;   // k = j      (bit3 = 0)
        float dhi = u[j] + z.x;   // k = j + 8  (bit3 = 1)
        e[j]     = exp2f(fmaf(dlo, pm, gv[j]     * qm));
        e[j + 8] = exp2f(fmaf(dhi, pm, gv[j + 8] * qm));
    }

    // Inverse butterfly: q_g = sum_k sign(k,g) e_k; denominator S is free.
    float p0 = e[0]  + e[1],  m0 = e[1]  - e[0];
    float p1 = e[2]  + e[3],  m1 = e[3]  - e[2];
    float p2 = e[4]  + e[5],  m2 = e[5]  - e[4];
    float p3 = e[6]  + e[7],  m3 = e[7]  - e[6];
    float p4 = e[8]  + e[9],  m4 = e[9]  - e[8];
    float p5 = e[10] + e[11], m5 = e[11] - e[10];
    float p6 = e[12] + e[13], m6 = e[13] - e[12];
    float p7 = e[14] + e[15], m7 = e[15] - e[14];

    float q3 = ((m0 + m1) + (m2 + m3)) + ((m4 + m5) + (m6 + m7)); // g=3

    float P0 = p0 + p1, M0 = p1 - p0;
    float P1 = p2 + p3, M1 = p3 - p2;
    float P2 = p4 + p5, M2 = p5 - p4;
    float P3 = p6 + p7, M3 = p7 - p6;

    float q2 = (M0 + M1) + (M2 + M3);                              // g=2

    float Q0 = P0 + P1, R0 = P1 - P0;
    float Q1 = P2 + P3, R1 = P3 - P2;

    float q1 = R0 + R1;                                            // g=1
    float q0 = Q1 - Q0;                                            // g=0
    float S  = Q0 + Q1;

    float rs = __frcp_rn(S);
    __stcs(&out[gid], make_float4(q0 * rs, q1 * rs, q2 * rs, q3 * rs));
}

// Fallback kernel with bounds check, used only if the element count is not an
// exact multiple of THREADS*4 (defensive; current shapes divide exactly).
__global__ void __launch_bounds__(THREADS)
gq_kernel_guard(const float4* __restrict__ x,
                const float4* __restrict__ gum,
                const float* __restrict__ log_temp,
                float4* __restrict__ out,
                int n_groups)
{
    int gid = blockIdx.x * THREADS + threadIdx.x;
    if (gid >= n_groups) return;

    float4 z  = __ldcs(&x[gid]);
    float4 g0 = __ldcs(&gum[gid * 4 + 0]);
    float4 g1 = __ldcs(&gum[gid * 4 + 1]);
    float4 g2 = __ldcs(&gum[gid * 4 + 2]);
    float4 g3 = __ldcs(&gum[gid * 4 + 3]);

    float tau = __expf(*log_temp);
    tau = fminf(fmaxf(tau, 0.05f), 5.0f);
    float it = __frcp_rn(tau);

    const float LOG2E = 1.4426950408889634f;
    float pm = 2.0f * it * LOG2E;
    float qm = it * LOG2E;

    float gv[16] = { g0.x, g0.y, g0.z, g0.w,
                     g1.x, g1.y, g1.z, g1.w,
                     g2.x, g2.y, g2.z, g2.w,
                     g3.x, g3.y, g3.z, g3.w };

    float t0 = -z.z - z.w;
    float t1 = -z.z + z.w;
    float t2 =  z.z - z.w;
    float t3 =  z.z + z.w;

    float u[8];
    u[0] = t0 - z.y;  u[1] = t1 - z.y;  u[2] = t2 - z.y;  u[3] = t3 - z.y;
    u[4] = t0 + z.y;  u[5] = t1 + z.y;  u[6] = t2 + z.y;  u[7] = t3 + z.y;

    float e[16];
#pragma unroll
    for (int j = 0; j < 8; j++) {
        float dlo = u[j] - z.x;
        float dhi = u[j] + z.x;
        e[j]     = exp2f(fmaf(dlo, pm, gv[j]     * qm));
        e[j + 8] = exp2f(fmaf(dhi, pm, gv[j + 8] * qm));
    }

    float p0 = e[0]  + e[1],  m0 = e[1]  - e[0];
    float p1 = e[2]  + e[3],  m1 = e[3]  - e[2];
    float p2 = e[4]  + e[5],  m2 = e[5]  - e[4];
    float p3 = e[6]  + e[7],  m3 = e[7]  - e[6];
    float p4 = e[8]  + e[9],  m4 = e[9]  - e[8];
    float p5 = e[10] + e[11], m5 = e[11] - e[10];
    float p6 = e[12] + e[13], m6 = e[13] - e[12];
    float p7 = e[14] + e[15], m7 = e[15] - e[14];

    float q3 = ((m0 + m1) + (m2 + m3)) + ((m4 + m5) + (m6 + m7));

    float P0 = p0 + p1, M0 = p1 - p0;
    float P1 = p2 + p3, M1 = p3 - p2;
    float P2 = p4 + p5, M2 = p5 - p4;
    float P3 = p6 + p7, M3 = p7 - p6;

    float q2 = (M0 + M1) + (M2 + M3);

    float Q0 = P0 + P1, R0 = P1 - P0;
    float Q1 = P2 + P3, R1 = P3 - P2;

    float q1 = R0 + R1;
    float q0 = Q1 - Q0;
    float S  = Q0 + Q1;

    float rs = __frcp_rn(S);
    __stcs(&out[gid], make_float4(q0 * rs, q1 * rs, q2 * rs, q3 * rs));
}

extern "C" void kernel_launch(void* const* d_in, const int* in_sizes, int n_in,
                              void* d_out, int out_size)
{
    const float* x        = (const float*)d_in[0];  // [B,S,D]
    const float* gumbel   = (const float*)d_in[1];  // [B,S,NG,NC]
    // d_in[2] = codebook: hypercube structure used analytically, no load
    const float* log_temp = (const float*)d_in[3];  // scalar

    float* out = (float*)d_out;

    int ng = in_sizes[0] / 4;   // 2,097,152 groups

    if (ng % THREADS == 0) {
        gq_kernel<<<ng / THREADS, THREADS>>>((const float4*)x,
                                             (const float4*)gumbel,
                                             log_temp,
                                             (float4*)out);
    } else {
        gq_kernel_guard<<<(ng + THREADS - 1) / THREADS, THREADS>>>(
            (const float4*)x, (const float4*)gumbel, log_temp,
            (float4*)out, ng);
    }
}